// round 1
// baseline (speedup 1.0000x reference)
#include <cuda_runtime.h>

// Problem constants
#define N_K   512      // codebook entries
#define DIM    64      // group size (vector dim)
#define NTILE 256      // codes per n-chunk
#define MTILE  64      // positions per block
#define RESULT_ELEMS 16777216   // 64*256*32*32

__device__ float g_h[N_K];   // 0.5 * ||e_k||^2

__global__ void compute_h_kernel(const float* __restrict__ w) {
    int k = threadIdx.x;
    if (k < N_K) {
        float s = 0.f;
        #pragma unroll
        for (int c = 0; c < DIM; ++c) {
            float v = w[c * N_K + k];
            s = fmaf(v, v, s);
        }
        g_h[k] = 0.5f * s;
    }
}

__global__ __launch_bounds__(256, 2)
void vq_kernel(const float* __restrict__ x, const float* __restrict__ w,
               float* __restrict__ out) {
    extern __shared__ float smem[];
    float* xs  = smem;                      // [DIM][MTILE]  16 KB
    float* es  = smem + DIM * MTILE;        // [DIM][NTILE]  64 KB
    float* hs  = es + DIM * NTILE;          // [NTILE]        1 KB
    int*   bks = (int*)(hs + NTILE);        // [MTILE]      256 B

    const int tid = threadIdx.x;
    const int bg  = blockIdx.x >> 4;        // (b, group)
    const int mb  = blockIdx.x & 15;        // which 64-position slab
    const int b   = bg >> 2;
    const int g   = bg & 3;
    const int hw0 = mb * 64;

    // ---- load x tile: xs[c][m] = x[b, g*64+c, hw0+m] (coalesced over m) ----
    const float* xbase = x + (b * 256 + g * 64) * 1024 + hw0;
    {
        int m  = tid & 63;
        int c0 = tid >> 6;
        #pragma unroll
        for (int i = 0; i < 16; ++i) {
            int c = c0 + i * 4;
            xs[c * 64 + m] = xbase[c * 1024 + m];
        }
    }

    const int tx = tid & 31;   // n-dimension lane
    const int ty = tid >> 5;   // m-dimension warp

    float bestv[8];
    int   bestk[8];
    #pragma unroll
    for (int i = 0; i < 8; ++i) { bestv[i] = -3.4e38f; bestk[i] = 0; }

    for (int nc = 0; nc < 2; ++nc) {
        const int koff = nc * NTILE;
        __syncthreads();   // previous chunk's es/hs reads done

        // ---- load e tile: es[c][kn] = w[c][koff+kn] (vectorized, coalesced) ----
        {
            int p  = tid & 63;
            int c0 = tid >> 6;
            #pragma unroll
            for (int i = 0; i < 16; ++i) {
                int c = c0 + i * 4;
                *(float4*)(es + c * NTILE + p * 4) =
                    *(const float4*)(w + c * N_K + koff + p * 4);
            }
            hs[tid] = g_h[koff + tid];
        }
        __syncthreads();

        // ---- 8x8 register-tiled GEMM over the 64-dim reduction ----
        float acc[8][8];
        #pragma unroll
        for (int i = 0; i < 8; ++i)
            #pragma unroll
            for (int j = 0; j < 8; ++j) acc[i][j] = 0.f;

        #pragma unroll 4
        for (int kk = 0; kk < DIM; ++kk) {
            float4 a0 = *(const float4*)(xs + kk * 64 + ty * 8);
            float4 a1 = *(const float4*)(xs + kk * 64 + ty * 8 + 4);
            float4 e0 = *(const float4*)(es + kk * NTILE + tx * 4);
            float4 e1 = *(const float4*)(es + kk * NTILE + 128 + tx * 4);
            float av[8] = {a0.x, a0.y, a0.z, a0.w, a1.x, a1.y, a1.z, a1.w};
            float ev[8] = {e0.x, e0.y, e0.z, e0.w, e1.x, e1.y, e1.z, e1.w};
            #pragma unroll
            for (int i = 0; i < 8; ++i)
                #pragma unroll
                for (int j = 0; j < 8; ++j)
                    acc[i][j] = fmaf(av[i], ev[j], acc[i][j]);
        }

        // ---- fused argmax epilogue: score = x.e - 0.5*||e||^2 ----
        #pragma unroll
        for (int j = 0; j < 8; ++j) {
            int n = (j < 4) ? (tx * 4 + j) : (128 + tx * 4 + (j - 4));
            float h = hs[n];
            int   k = koff + n;
            #pragma unroll
            for (int i = 0; i < 8; ++i) {
                float s = acc[i][j] - h;
                if (s > bestv[i]) { bestv[i] = s; bestk[i] = k; }
            }
        }
    }

    // ---- per-warp reduction: each warp (fixed ty) owns 8 m-rows; lanes = tx ----
    #pragma unroll
    for (int i = 0; i < 8; ++i) {
        float v = bestv[i];
        int   k = bestk[i];
        #pragma unroll
        for (int off = 16; off > 0; off >>= 1) {
            float ov = __shfl_xor_sync(0xffffffffu, v, off);
            int   ok = __shfl_xor_sync(0xffffffffu, k, off);
            if (ov > v || (ov == v && ok < k)) { v = ov; k = ok; }
        }
        if (tx == 0) bks[ty * 8 + i] = k;
    }
    __syncthreads();

    // ---- write argmins (as float, after the 16.7M-element result section) ----
    if (tid < 64) {
        out[RESULT_ELEMS + (b * 4 + g) * 1024 + hw0 + tid] = (float)bks[tid];
    }

    // ---- write result: out[b, g*64+c, hw0+m] = w[c][k[m]] * 0.5 (coalesced) ----
    float* obase = out + (b * 256 + g * 64) * 1024 + hw0;
    {
        int m  = tid & 63;
        int c0 = tid >> 6;
        int k  = bks[m];
        #pragma unroll
        for (int i = 0; i < 16; ++i) {
            int c = c0 + i * 4;
            obase[c * 1024 + m] = w[c * N_K + k] * 0.5f;
        }
    }
}

extern "C" void kernel_launch(void* const* d_in, const int* in_sizes, int n_in,
                              void* d_out, int out_size) {
    const float* x = (const float*)d_in[0];   // (64, 256, 32, 32) fp32
    const float* w = (const float*)d_in[1];   // (64, 512) fp32
    float* out = (float*)d_out;               // result (16.7M) ++ argmins (262K)

    const int smem_bytes = (DIM * MTILE + DIM * NTILE + NTILE) * 4 + MTILE * 4;
    cudaFuncSetAttribute(vq_kernel, cudaFuncAttributeMaxDynamicSharedMemorySize,
                         smem_bytes);

    compute_h_kernel<<<1, N_K>>>(w);
    // 64 batches * 4 groups * 16 m-slabs = 4096 blocks
    vq_kernel<<<4096, 256, smem_bytes>>>(x, w, out);
}